// round 4
// baseline (speedup 1.0000x reference)
#include <cuda_runtime.h>

// ConvCapsMatrix: EM-routing matrix capsules, fully fused single kernel.
// B=4, H=W=14 -> Ho=Wo=12, KH=KW=3, IC=OC=32, M=4 (P=16), ITERS=3.
//
// Fusions:
//  - sig2 = E[V^2] - mu^2 (one pass over V per EM iteration)
//  - R-update of iter i fused into mu/sig accumulation pass of iter i+1
//  - V recomputed per pass from smem x-patch + L2-resident W (never stored)
//  - all pose-dim (P=16) math done as packed f32x2 (Blackwell FFMA2)
// Roles in a 512-thread CTA (one CTA per output position):
//  streaming: (nn = warp 0..15, o = lane 0..31); softmax over o = warp shfl
//  stats:     (o3 = tid>>4, p3 = tid&15)

#define NPOS  576           // 4 * 12 * 12
#define EPSF  1e-8f

typedef unsigned long long u64;

__device__ __forceinline__ u64 pk2(float lo, float hi) {
    u64 r; asm("mov.b64 %0, {%1, %2};" : "=l"(r) : "f"(lo), "f"(hi)); return r;
}
__device__ __forceinline__ void upk2(u64 v, float& lo, float& hi) {
    asm("mov.b64 {%0, %1}, %2;" : "=f"(lo), "=f"(hi) : "l"(v));
}
__device__ __forceinline__ u64 fma2(u64 a, u64 b, u64 c) {
    u64 d; asm("fma.rn.f32x2 %0, %1, %2, %3;" : "=l"(d) : "l"(a), "l"(b), "l"(c)); return d;
}
__device__ __forceinline__ u64 mul2(u64 a, u64 b) {
    u64 d; asm("mul.rn.f32x2 %0, %1, %2;" : "=l"(d) : "l"(a), "l"(b)); return d;
}
__device__ __forceinline__ u64 add2(u64 a, u64 b) {
    u64 d; asm("add.rn.f32x2 %0, %1, %2;" : "=l"(d) : "l"(a), "l"(b)); return d;
}

__global__ void __launch_bounds__(512)
caps_kernel(const float* __restrict__ x, const float* __restrict__ a,
            const float* __restrict__ W, const float* __restrict__ bu_g,
            const float* __restrict__ ba_g, float* __restrict__ out)
{
    __shared__ __align__(16) float xp_s[4608];   // x patch: [n][x*4+y]
    __shared__ float a_s[288];                   // a patch: [n]
    __shared__ float S1_s[544];                  // [o*17+p] stride-17 (conflict-free atomics)
    __shared__ float S2_s[544];
    __shared__ float Rs_s[32];
    __shared__ __align__(16) float nmu_s[576];   // -mu, [o*18+p] (pair-readable, stride 9 u64)
    __shared__ __align__(16) float hisg_s[576];  // 0.5/sig2, same layout
    __shared__ float slog_s[32];
    __shared__ float loga_s[32];

    const int tid = threadIdx.x;
    const int pos = blockIdx.x;
    const int b  = pos / 144;
    const int hw = pos - b * 144;
    const int h  = hw / 12;
    const int w  = hw - h * 12;

    // ---- load x / a patches into smem (coalesced) ----
    for (int idx = tid; idx < 4608; idx += 512) {
        int n = idx >> 4, q = idx & 15;
        int k = n / 96;
        int r = n - k * 96;
        int l = r >> 5;
        int c = r & 31;
        xp_s[idx] = x[(((b * 14 + h + k) * 14 + (w + l)) * 32 + c) * 16 + q];
    }
    if (tid < 288) {
        int n = tid;
        int k = n / 96;
        int r = n - k * 96;
        int l = r >> 5;
        int c = r & 31;
        a_s[n] = a[((b * 14 + h + k) * 14 + (w + l)) * 32 + c];
    }
    __syncthreads();

    const int lane_o  = tid & 31;   // streaming: output capsule
    const int warp_nn = tid >> 5;   // streaming: n within chunk
    const int o3 = tid >> 4;        // stats role
    const int p3 = tid & 15;

    const u64* nmu_p = reinterpret_cast<const u64*>(nmu_s)  + lane_o * 9;
    const u64* hsg_p = reinterpret_cast<const u64*>(hisg_s) + lane_o * 9;

    for (int pass = 0; pass < 3; ++pass) {
        // zero reduction buffers
        for (int i = tid; i < 1120; i += 512) {
            if (i < 544)       S1_s[i] = 0.f;
            else if (i < 1088) S2_s[i - 544] = 0.f;
            else               Rs_s[i - 1088] = 0.f;
        }
        __syncthreads();

        u64 s1p[8], s2p[8];
        #pragma unroll
        for (int j = 0; j < 8; ++j) { s1p[j] = 0ull; s2p[j] = 0ull; }
        float rs_reg = 0.f;

        // pre = log(a_out) - 0.5 * sum_p log sig2   (per o, constant over chunk loop)
        const float pre = (pass > 0) ? (loga_s[lane_o] - 0.5f * slog_s[lane_o]) : 0.f;

        #pragma unroll 1
        for (int ch = 0; ch < 18; ++ch) {
            const int n = ch * 16 + warp_nn;

            // W row (n, lane_o): 16 floats = 4 y-rows of ((z0,z1),(z2,z3)) pairs
            const ulonglong2* Wp =
                reinterpret_cast<const ulonglong2*>(W) + ((n << 5) + lane_o) * 4;
            ulonglong2 wy0 = Wp[0], wy1 = Wp[1], wy2 = Wp[2], wy3 = Wp[3];

            const float4* xv = reinterpret_cast<const float4*>(xp_s) + (n << 2);

            // V[n, lane_o, :] packed: vp[2x+h] = (v[4x+2h], v[4x+2h+1])
            u64 vp[8];
            #pragma unroll
            for (int xx = 0; xx < 4; ++xx) {
                float4 xr = xv[xx];
                u64 b0 = pk2(xr.x, xr.x);
                u64 b1 = pk2(xr.y, xr.y);
                u64 b2 = pk2(xr.z, xr.z);
                u64 b3 = pk2(xr.w, xr.w);
                u64 lo = mul2(b0, wy0.x);
                lo = fma2(b1, wy1.x, lo);
                lo = fma2(b2, wy2.x, lo);
                lo = fma2(b3, wy3.x, lo);
                u64 hi = mul2(b0, wy0.y);
                hi = fma2(b1, wy1.y, hi);
                hi = fma2(b2, wy2.y, hi);
                hi = fma2(b3, wy3.y, hi);
                vp[xx * 2]     = lo;
                vp[xx * 2 + 1] = hi;
            }

            float Ra;
            if (pass == 0) {
                Ra = a_s[n] * 0.03125f;   // R uniform = 1/OC
            } else {
                // t = sum_p 0.5 * d^2 / sig2   (0.5 folded into stored hisg)
                u64 t2 = 0ull;
                #pragma unroll
                for (int j = 0; j < 8; ++j) {
                    u64 d = add2(vp[j], nmu_p[j]);   // mu stored negated
                    t2 = fma2(mul2(d, d), hsg_p[j], t2);
                }
                float tl, th; upk2(t2, tl, th);
                float s = pre - (tl + th);
                // softmax over o == softmax over warp lanes
                float m = s;
                #pragma unroll
                for (int off = 16; off; off >>= 1)
                    m = fmaxf(m, __shfl_xor_sync(0xffffffffu, m, off));
                float e = __expf(s - m);
                float sum = e;
                #pragma unroll
                for (int off = 16; off; off >>= 1)
                    sum += __shfl_xor_sync(0xffffffffu, sum, off);
                Ra = __fdividef(e, sum) * a_s[n];
            }

            rs_reg += Ra;
            u64 Ra2 = pk2(Ra, Ra);
            #pragma unroll
            for (int j = 0; j < 8; ++j) {
                u64 rv = mul2(Ra2, vp[j]);
                s1p[j] = add2(s1p[j], rv);
                s2p[j] = fma2(rv, vp[j], s2p[j]);
            }
        }

        // cross-warp reduction (stride-17 -> o*17+p is a bank bijection per warp)
        atomicAdd(&Rs_s[lane_o], rs_reg);
        #pragma unroll
        for (int j = 0; j < 8; ++j) {
            float lo, hi;
            upk2(s1p[j], lo, hi);
            atomicAdd(&S1_s[lane_o * 17 + 2 * j],     lo);
            atomicAdd(&S1_s[lane_o * 17 + 2 * j + 1], hi);
            upk2(s2p[j], lo, hi);
            atomicAdd(&S2_s[lane_o * 17 + 2 * j],     lo);
            atomicAdd(&S2_s[lane_o * 17 + 2 * j + 1], hi);
        }
        __syncthreads();

        // ---- stats: thread (o3, p3) ----
        float Rsv   = Rs_s[o3] + EPSF;
        float invRs = 1.0f / Rsv;
        float mu    = S1_s[o3 * 17 + p3] * invRs;
        float sig2  = fmaxf(S2_s[o3 * 17 + p3] * invRs - mu * mu, 0.0f) + EPSF;
        float sl    = __logf(sig2);
        #pragma unroll
        for (int off = 8; off; off >>= 1)     // reduce log sig2 over the 16 p-lanes
            sl += __shfl_xor_sync(0xffffffffu, sl, off);

        if (pass < 2) {
            nmu_s[o3 * 18 + p3]  = -mu;
            hisg_s[o3 * 18 + p3] = __fdividef(0.5f, sig2);
            if (p3 == 0) {
                slog_s[o3] = sl;
                float cost = Rsv * fmaf(0.5f, sl, 16.0f * bu_g[o3]);
                float aout = 1.0f / (1.0f + __expf(cost - ba_g[o3]));
                loga_s[o3] = __logf(aout + EPSF);
            }
            __syncthreads();   // stats reads done before next pass's zeroing
        } else {
            // final iteration: emit pose (= mu) and activation
            out[pos * 512 + o3 * 16 + p3] = mu;
            if (p3 == 0) {
                float cost = Rsv * fmaf(0.5f, sl, 16.0f * bu_g[o3]);
                out[NPOS * 512 + pos * 32 + o3] =
                    1.0f / (1.0f + __expf(cost - ba_g[o3]));
            }
        }
    }
}

extern "C" void kernel_launch(void* const* d_in, const int* in_sizes, int n_in,
                              void* d_out, int out_size)
{
    (void)in_sizes; (void)n_in; (void)out_size;
    const float* x  = (const float*)d_in[0];
    const float* a  = (const float*)d_in[1];
    const float* W  = (const float*)d_in[2];
    const float* bu = (const float*)d_in[3];
    const float* ba = (const float*)d_in[4];
    caps_kernel<<<NPOS, 512>>>(x, a, W, bu, ba, (float*)d_out);
}

// round 5
// speedup vs baseline: 1.0093x; 1.0093x over previous
#include <cuda_runtime.h>

// ConvCapsMatrix: EM-routing matrix capsules, fully fused single kernel.
// B=4, H=W=14 -> Ho=Wo=12, KH=KW=3, IC=OC=32, M=4 (P=16), ITERS=3.
//
// R4 -> R5: the smem-atomic cross-warp reduction (33 ATOMS/thread/pass,
// ~64 LSU-cyc each) was 70%+ of runtime (l1tex=72.8%). Replaced with
// STS-scatter to per-warp stride-17 rows + LDS-gather (conflict-light),
// dynamic smem (~94KB). Also pipelined W loads one half-iteration ahead.
//
// Fusions (unchanged): sig2 = E[V^2]-mu^2; R-update of iter i fused into
// accumulation of iter i+1; V recomputed per pass (never stored); all
// pose-dim math packed f32x2.
// Roles in a 512-thread CTA (one CTA per output position):
//  streaming: (nn = warp 0..15, o = lane 0..31); softmax over o = warp shfl
//  stats:     (o3 = tid>>4, p3 = tid&15)

#define NPOS  576           // 4 * 12 * 12
#define EPSF  1e-8f

// dynamic smem layout (float offsets)
#define SM_XP    0          // [4608]  x patch [n][p]
#define SM_A     4608       // [288]   a patch
#define SM_NMU   4896       // [576]   -mu, [o*18+p] (u64-pair readable)
#define SM_HSG   5472       // [576]   0.5/sig2, same layout
#define SM_SLOG  6048       // [32]
#define SM_LOGA  6080       // [32]
#define SM_RED1  6112       // [16*544] per-warp S1 partials [w*544+o*17+p], p=16 -> Rs
#define SM_RED2  14816      // [16*544] per-warp S2 partials
#define SM_TOT   23520      // floats -> 94080 bytes

typedef unsigned long long u64;

__device__ __forceinline__ u64 pk2(float lo, float hi) {
    u64 r; asm("mov.b64 %0, {%1, %2};" : "=l"(r) : "f"(lo), "f"(hi)); return r;
}
__device__ __forceinline__ void upk2(u64 v, float& lo, float& hi) {
    asm("mov.b64 {%0, %1}, %2;" : "=f"(lo), "=f"(hi) : "l"(v));
}
__device__ __forceinline__ u64 fma2(u64 a, u64 b, u64 c) {
    u64 d; asm("fma.rn.f32x2 %0, %1, %2, %3;" : "=l"(d) : "l"(a), "l"(b), "l"(c)); return d;
}
__device__ __forceinline__ u64 mul2(u64 a, u64 b) {
    u64 d; asm("mul.rn.f32x2 %0, %1, %2;" : "=l"(d) : "l"(a), "l"(b)); return d;
}
__device__ __forceinline__ u64 add2(u64 a, u64 b) {
    u64 d; asm("add.rn.f32x2 %0, %1, %2;" : "=l"(d) : "l"(a), "l"(b)); return d;
}

extern __shared__ float smem[];

__global__ void __launch_bounds__(512)
caps_kernel(const float* __restrict__ x, const float* __restrict__ a,
            const float* __restrict__ W, const float* __restrict__ bu_g,
            const float* __restrict__ ba_g, float* __restrict__ out)
{
    const int tid = threadIdx.x;
    const int pos = blockIdx.x;
    const int b  = pos / 144;
    const int hw = pos - b * 144;
    const int h  = hw / 12;
    const int w  = hw - h * 12;

    // ---- load x / a patches into smem (coalesced) ----
    for (int idx = tid; idx < 4608; idx += 512) {
        int n = idx >> 4, q = idx & 15;
        int k = n / 96;
        int r = n - k * 96;
        int l = r >> 5;
        int c = r & 31;
        smem[SM_XP + idx] = x[(((b * 14 + h + k) * 14 + (w + l)) * 32 + c) * 16 + q];
    }
    if (tid < 288) {
        int n = tid;
        int k = n / 96;
        int r = n - k * 96;
        int l = r >> 5;
        int c = r & 31;
        smem[SM_A + n] = a[((b * 14 + h + k) * 14 + (w + l)) * 32 + c];
    }
    __syncthreads();

    const int lane_o  = tid & 31;   // streaming: output capsule
    const int warp_nn = tid >> 5;   // streaming: n within chunk
    const int o3 = tid >> 4;        // stats role
    const int p3 = tid & 15;

    const u64* nmu_p = reinterpret_cast<const u64*>(smem + SM_NMU) + lane_o * 9;
    const u64* hsg_p = reinterpret_cast<const u64*>(smem + SM_HSG) + lane_o * 9;
    float* row1 = smem + SM_RED1 + warp_nn * 544 + lane_o * 17;  // bank-bijective over o
    float* row2 = smem + SM_RED2 + warp_nn * 544 + lane_o * 17;
    // W for (chunk-chunk n = ch*16 + warp_nn, o = lane_o): base + ch * 2048 ull2
    const ulonglong2* Wbase =
        reinterpret_cast<const ulonglong2*>(W) + ((warp_nn << 5) + lane_o) * 4;

    for (int pass = 0; pass < 3; ++pass) {
        u64 s1p[8], s2p[8];
        #pragma unroll
        for (int j = 0; j < 8; ++j) { s1p[j] = 0ull; s2p[j] = 0ull; }
        float rs_reg = 0.f;

        // pre = log(a_out) - 0.5 * sum_p log sig2  (constant over chunks)
        const float pre = (pass > 0)
            ? (smem[SM_LOGA + lane_o] - 0.5f * smem[SM_SLOG + lane_o]) : 0.f;

        // prefetch chunk 0's W row
        const ulonglong2* wp = Wbase;
        ulonglong2 wy0 = wp[0], wy1 = wp[1], wy2 = wp[2], wy3 = wp[3];

        #pragma unroll 1
        for (int ch = 0; ch < 18; ++ch) {
            const int n = ch * 16 + warp_nn;
            const float4* xv = reinterpret_cast<const float4*>(smem + SM_XP) + (n << 2);

            // V[n, lane_o, :] packed: vp[2x+hh] = (v[4x+2hh], v[4x+2hh+1])
            u64 vp[8];
            #pragma unroll
            for (int xx = 0; xx < 4; ++xx) {
                float4 xr = xv[xx];
                u64 b0 = pk2(xr.x, xr.x);
                u64 b1 = pk2(xr.y, xr.y);
                u64 b2 = pk2(xr.z, xr.z);
                u64 b3 = pk2(xr.w, xr.w);
                u64 lo = mul2(b0, wy0.x);
                lo = fma2(b1, wy1.x, lo);
                lo = fma2(b2, wy2.x, lo);
                lo = fma2(b3, wy3.x, lo);
                u64 hi = mul2(b0, wy0.y);
                hi = fma2(b1, wy1.y, hi);
                hi = fma2(b2, wy2.y, hi);
                hi = fma2(b3, wy3.y, hi);
                vp[xx * 2]     = lo;
                vp[xx * 2 + 1] = hi;
            }

            // wy dead: issue next chunk's W loads now (covered by logp/softmax/accum)
            if (ch < 17) {
                wp += 2048;
                wy0 = wp[0]; wy1 = wp[1]; wy2 = wp[2]; wy3 = wp[3];
            }

            float Ra;
            if (pass == 0) {
                Ra = smem[SM_A + n] * 0.03125f;   // R uniform = 1/OC
            } else {
                // t = sum_p 0.5 * d^2 / sig2  (0.5 folded into hisg)
                u64 t2 = 0ull;
                #pragma unroll
                for (int j = 0; j < 8; ++j) {
                    u64 d = add2(vp[j], nmu_p[j]);   // mu stored negated
                    t2 = fma2(mul2(d, d), hsg_p[j], t2);
                }
                float tl, th; upk2(t2, tl, th);
                float s = pre - (tl + th);
                // softmax over o == softmax over warp lanes
                float m = s;
                #pragma unroll
                for (int off = 16; off; off >>= 1)
                    m = fmaxf(m, __shfl_xor_sync(0xffffffffu, m, off));
                float e = __expf(s - m);
                float sum = e;
                #pragma unroll
                for (int off = 16; off; off >>= 1)
                    sum += __shfl_xor_sync(0xffffffffu, sum, off);
                Ra = __fdividef(e, sum) * smem[SM_A + n];
            }

            rs_reg += Ra;
            u64 Ra2 = pk2(Ra, Ra);
            #pragma unroll
            for (int j = 0; j < 8; ++j) {
                u64 rv = mul2(Ra2, vp[j]);
                s1p[j] = add2(s1p[j], rv);
                s2p[j] = fma2(rv, vp[j], s2p[j]);
            }
        }

        // ---- cross-warp reduction: STS partials to this warp's private row ----
        row1[16] = rs_reg;                   // Rs in the p=16 pad slot
        #pragma unroll
        for (int j = 0; j < 8; ++j) {
            float lo, hi;
            upk2(s1p[j], lo, hi);
            row1[2 * j] = lo; row1[2 * j + 1] = hi;
            upk2(s2p[j], lo, hi);
            row2[2 * j] = lo; row2[2 * j + 1] = hi;
        }
        __syncthreads();

        // ---- gather + stats: thread (o3, p3) ----
        float sS1 = 0.f, sS2 = 0.f, sRs = 0.f;
        {
            const float* g1 = smem + SM_RED1 + o3 * 17 + p3;
            const float* g2 = smem + SM_RED2 + o3 * 17 + p3;
            const float* gr = smem + SM_RED1 + o3 * 17 + 16;
            #pragma unroll
            for (int ww = 0; ww < 16; ++ww) {
                sS1 += g1[ww * 544];
                sS2 += g2[ww * 544];
                sRs += gr[ww * 544];
            }
        }
        float Rsv   = sRs + EPSF;
        float invRs = 1.0f / Rsv;
        float mu    = sS1 * invRs;
        float sig2  = fmaxf(sS2 * invRs - mu * mu, 0.0f) + EPSF;
        float sl    = __logf(sig2);
        #pragma unroll
        for (int off = 8; off; off >>= 1)     // reduce log sig2 over 16 p-lanes
            sl += __shfl_xor_sync(0xffffffffu, sl, off);

        if (pass < 2) {
            smem[SM_NMU + o3 * 18 + p3] = -mu;
            smem[SM_HSG + o3 * 18 + p3] = __fdividef(0.5f, sig2);
            if (p3 == 0) {
                smem[SM_SLOG + o3] = sl;
                float cost = Rsv * fmaf(0.5f, sl, 16.0f * bu_g[o3]);
                float aout = 1.0f / (1.0f + __expf(cost - ba_g[o3]));
                smem[SM_LOGA + o3] = __logf(aout + EPSF);
            }
            __syncthreads();   // stats visible before next pass streams
        } else {
            // final iteration: emit pose (= mu) and activation
            out[pos * 512 + o3 * 16 + p3] = mu;
            if (p3 == 0) {
                float cost = Rsv * fmaf(0.5f, sl, 16.0f * bu_g[o3]);
                out[NPOS * 512 + pos * 32 + o3] =
                    1.0f / (1.0f + __expf(cost - ba_g[o3]));
            }
        }
    }
}

extern "C" void kernel_launch(void* const* d_in, const int* in_sizes, int n_in,
                              void* d_out, int out_size)
{
    (void)in_sizes; (void)n_in; (void)out_size;
    const float* x  = (const float*)d_in[0];
    const float* a  = (const float*)d_in[1];
    const float* W  = (const float*)d_in[2];
    const float* bu = (const float*)d_in[3];
    const float* ba = (const float*)d_in[4];
    cudaFuncSetAttribute(caps_kernel,
                         cudaFuncAttributeMaxDynamicSharedMemorySize,
                         SM_TOT * (int)sizeof(float));
    caps_kernel<<<NPOS, 512, SM_TOT * sizeof(float)>>>(x, a, W, bu, ba, (float*)d_out);
}

// round 6
// speedup vs baseline: 1.4278x; 1.4146x over previous
#include <cuda_runtime.h>

// ConvCapsMatrix: EM-routing matrix capsules, fully fused.
// B=4, 14x14 -> 12x12, KH=KW=3, IC=OC=32, M=4 (P=16), ITERS=3.
//
// R5 -> R6: ncu showed L1tex=74% binding; root cause is W gather — thread
// (n,o) reads its own 64B row => each LDG.128 hits 16 lines (16 wavefronts).
// Fix: pre-transpose W (tiny helper kernel, __device__ scratch) to
// Wt[(n*4+y)*32+o] so lanes (=o) read consecutive 16B: 4 lines per LDG,
// 4x fewer L1 wavefronts. fp32-FMA pipe becomes the binding resource.
//
// Fusions: sig2 = E[V^2]-mu^2; R-update of iter i fused into accumulation
// of iter i+1; V recomputed per pass (never stored); pose math packed f32x2.
// Roles in a 512-thread CTA (one CTA per output position):
//  streaming: (nn = warp 0..15, o = lane 0..31); softmax over o = warp shfl
//  stats:     (o3 = tid>>4, p3 = tid&15)

#define NPOS  576           // 4 * 12 * 12
#define EPSF  1e-8f

// dynamic smem layout (float offsets)
#define SM_XP    0          // [4608]  x patch [n][p]
#define SM_A     4608       // [288]   a patch
#define SM_NMU   4896       // [576]   -mu, [o*18+p] (u64-pair readable)
#define SM_HSG   5472       // [576]   0.5/sig2, same layout
#define SM_SLOG  6048       // [32]
#define SM_LOGA  6080       // [32]
#define SM_RED1  6112       // [16*544] per-warp S1 partials [w*544+o*17+p], p=16 -> Rs
#define SM_RED2  14816      // [16*544] per-warp S2 partials
#define SM_TOT   23520      // floats -> 94080 bytes

typedef unsigned long long u64;

// transposed W: ulonglong2[(n*4+y)*32 + o] = W[n][o][y][0..3]  (576 KB scratch)
__device__ ulonglong2 g_Wt[288 * 4 * 32];

__device__ __forceinline__ u64 pk2(float lo, float hi) {
    u64 r; asm("mov.b64 %0, {%1, %2};" : "=l"(r) : "f"(lo), "f"(hi)); return r;
}
__device__ __forceinline__ void upk2(u64 v, float& lo, float& hi) {
    asm("mov.b64 {%0, %1}, %2;" : "=f"(lo), "=f"(hi) : "l"(v));
}
__device__ __forceinline__ u64 fma2(u64 a, u64 b, u64 c) {
    u64 d; asm("fma.rn.f32x2 %0, %1, %2, %3;" : "=l"(d) : "l"(a), "l"(b), "l"(c)); return d;
}
__device__ __forceinline__ u64 mul2(u64 a, u64 b) {
    u64 d; asm("mul.rn.f32x2 %0, %1, %2;" : "=l"(d) : "l"(a), "l"(b)); return d;
}
__device__ __forceinline__ u64 add2(u64 a, u64 b) {
    u64 d; asm("add.rn.f32x2 %0, %1, %2;" : "=l"(d) : "l"(a), "l"(b)); return d;
}

__global__ void __launch_bounds__(256)
transpose_W_kernel(const float4* __restrict__ W4)
{
    int idx = blockIdx.x * 256 + threadIdx.x;   // (n*4+y)*32 + o
    if (idx >= 288 * 4 * 32) return;
    int o  = idx & 31;
    int ny = idx >> 5;
    int y  = ny & 3;
    int n  = ny >> 2;
    float4 r = W4[(n * 32 + o) * 4 + y];
    ulonglong2 v;
    v.x = pk2(r.x, r.y);
    v.y = pk2(r.z, r.w);
    g_Wt[idx] = v;                               // coalesced 16B store
}

extern __shared__ float smem[];

__global__ void __launch_bounds__(512)
caps_kernel(const float* __restrict__ x, const float* __restrict__ a,
            const float* __restrict__ bu_g, const float* __restrict__ ba_g,
            float* __restrict__ out)
{
    const int tid = threadIdx.x;
    const int pos = blockIdx.x;
    const int b  = pos / 144;
    const int hw = pos - b * 144;
    const int h  = hw / 12;
    const int w  = hw - h * 12;

    // ---- load x / a patches into smem (coalesced) ----
    for (int idx = tid; idx < 4608; idx += 512) {
        int n = idx >> 4, q = idx & 15;
        int k = n / 96;
        int r = n - k * 96;
        int l = r >> 5;
        int c = r & 31;
        smem[SM_XP + idx] = x[(((b * 14 + h + k) * 14 + (w + l)) * 32 + c) * 16 + q];
    }
    if (tid < 288) {
        int n = tid;
        int k = n / 96;
        int r = n - k * 96;
        int l = r >> 5;
        int c = r & 31;
        smem[SM_A + n] = a[((b * 14 + h + k) * 14 + (w + l)) * 32 + c];
    }
    __syncthreads();

    const int lane_o  = tid & 31;   // streaming: output capsule
    const int warp_nn = tid >> 5;   // streaming: n within chunk
    const int o3 = tid >> 4;        // stats role
    const int p3 = tid & 15;

    const u64* nmu_p = reinterpret_cast<const u64*>(smem + SM_NMU) + lane_o * 9;
    const u64* hsg_p = reinterpret_cast<const u64*>(smem + SM_HSG) + lane_o * 9;
    float* row1 = smem + SM_RED1 + warp_nn * 544 + lane_o * 17;  // bank-bijective over o
    float* row2 = smem + SM_RED2 + warp_nn * 544 + lane_o * 17;
    // coalesced W: lane o reads g_Wt[(n*4+y)*32 + o]; chunk stride = 16*4*32
    const ulonglong2* Wbase = g_Wt + (warp_nn << 7) + lane_o;

    for (int pass = 0; pass < 3; ++pass) {
        u64 s1p[8], s2p[8];
        #pragma unroll
        for (int j = 0; j < 8; ++j) { s1p[j] = 0ull; s2p[j] = 0ull; }
        float rs_reg = 0.f;

        // pre = log(a_out) - 0.5 * sum_p log sig2  (constant over chunks)
        const float pre = (pass > 0)
            ? (smem[SM_LOGA + lane_o] - 0.5f * smem[SM_SLOG + lane_o]) : 0.f;

        // prefetch chunk 0's W rows (4 coalesced LDG.128)
        const ulonglong2* wp = Wbase;
        ulonglong2 wy0 = wp[0], wy1 = wp[32], wy2 = wp[64], wy3 = wp[96];

        #pragma unroll 1
        for (int ch = 0; ch < 18; ++ch) {
            const int n = ch * 16 + warp_nn;
            const float4* xv = reinterpret_cast<const float4*>(smem + SM_XP) + (n << 2);

            // V[n, lane_o, :] packed: vp[2x+hh] = (v[4x+2hh], v[4x+2hh+1])
            u64 vp[8];
            #pragma unroll
            for (int xx = 0; xx < 4; ++xx) {
                float4 xr = xv[xx];
                u64 b0 = pk2(xr.x, xr.x);
                u64 b1 = pk2(xr.y, xr.y);
                u64 b2 = pk2(xr.z, xr.z);
                u64 b3 = pk2(xr.w, xr.w);
                u64 lo = mul2(b0, wy0.x);
                lo = fma2(b1, wy1.x, lo);
                lo = fma2(b2, wy2.x, lo);
                lo = fma2(b3, wy3.x, lo);
                u64 hi = mul2(b0, wy0.y);
                hi = fma2(b1, wy1.y, hi);
                hi = fma2(b2, wy2.y, hi);
                hi = fma2(b3, wy3.y, hi);
                vp[xx * 2]     = lo;
                vp[xx * 2 + 1] = hi;
            }

            // wy dead: issue next chunk's W loads now (covered by logp/softmax/accum)
            if (ch < 17) {
                wp += 2048;
                wy0 = wp[0]; wy1 = wp[32]; wy2 = wp[64]; wy3 = wp[96];
            }

            float Ra;
            if (pass == 0) {
                Ra = smem[SM_A + n] * 0.03125f;   // R uniform = 1/OC
            } else {
                // t = sum_p 0.5 * d^2 / sig2  (0.5 folded into hisg)
                u64 t2 = 0ull;
                #pragma unroll
                for (int j = 0; j < 8; ++j) {
                    u64 d = add2(vp[j], nmu_p[j]);   // mu stored negated
                    t2 = fma2(mul2(d, d), hsg_p[j], t2);
                }
                float tl, th; upk2(t2, tl, th);
                float s = pre - (tl + th);
                // softmax over o == softmax over warp lanes
                float m = s;
                #pragma unroll
                for (int off = 16; off; off >>= 1)
                    m = fmaxf(m, __shfl_xor_sync(0xffffffffu, m, off));
                float e = __expf(s - m);
                float sum = e;
                #pragma unroll
                for (int off = 16; off; off >>= 1)
                    sum += __shfl_xor_sync(0xffffffffu, sum, off);
                Ra = __fdividef(e, sum) * smem[SM_A + n];
            }

            rs_reg += Ra;
            u64 Ra2 = pk2(Ra, Ra);
            #pragma unroll
            for (int j = 0; j < 8; ++j) {
                u64 rv = mul2(Ra2, vp[j]);
                s1p[j] = add2(s1p[j], rv);
                s2p[j] = fma2(rv, vp[j], s2p[j]);
            }
        }

        // ---- cross-warp reduction: STS partials to this warp's private row ----
        row1[16] = rs_reg;                   // Rs in the p=16 pad slot
        #pragma unroll
        for (int j = 0; j < 8; ++j) {
            float lo, hi;
            upk2(s1p[j], lo, hi);
            row1[2 * j] = lo; row1[2 * j + 1] = hi;
            upk2(s2p[j], lo, hi);
            row2[2 * j] = lo; row2[2 * j + 1] = hi;
        }
        __syncthreads();

        // ---- gather + stats: thread (o3, p3) ----
        float sS1 = 0.f, sS2 = 0.f, sRs = 0.f;
        {
            const float* g1 = smem + SM_RED1 + o3 * 17 + p3;
            const float* g2 = smem + SM_RED2 + o3 * 17 + p3;
            const float* gr = smem + SM_RED1 + o3 * 17 + 16;
            #pragma unroll
            for (int ww = 0; ww < 16; ++ww) {
                sS1 += g1[ww * 544];
                sS2 += g2[ww * 544];
                sRs += gr[ww * 544];
            }
        }
        float Rsv   = sRs + EPSF;
        float invRs = 1.0f / Rsv;
        float mu    = sS1 * invRs;
        float sig2  = fmaxf(sS2 * invRs - mu * mu, 0.0f) + EPSF;
        float sl    = __logf(sig2);
        #pragma unroll
        for (int off = 8; off; off >>= 1)     // reduce log sig2 over 16 p-lanes
            sl += __shfl_xor_sync(0xffffffffu, sl, off);

        if (pass < 2) {
            smem[SM_NMU + o3 * 18 + p3] = -mu;
            smem[SM_HSG + o3 * 18 + p3] = __fdividef(0.5f, sig2);
            if (p3 == 0) {
                smem[SM_SLOG + o3] = sl;
                float cost = Rsv * fmaf(0.5f, sl, 16.0f * bu_g[o3]);
                float aout = 1.0f / (1.0f + __expf(cost - ba_g[o3]));
                smem[SM_LOGA + o3] = __logf(aout + EPSF);
            }
            __syncthreads();   // stats visible before next pass streams
        } else {
            // final iteration: emit pose (= mu) and activation
            out[pos * 512 + o3 * 16 + p3] = mu;
            if (p3 == 0) {
                float cost = Rsv * fmaf(0.5f, sl, 16.0f * bu_g[o3]);
                out[NPOS * 512 + pos * 32 + o3] =
                    1.0f / (1.0f + __expf(cost - ba_g[o3]));
            }
        }
    }
}

extern "C" void kernel_launch(void* const* d_in, const int* in_sizes, int n_in,
                              void* d_out, int out_size)
{
    (void)in_sizes; (void)n_in; (void)out_size;
    const float* x  = (const float*)d_in[0];
    const float* a  = (const float*)d_in[1];
    const float* W  = (const float*)d_in[2];
    const float* bu = (const float*)d_in[3];
    const float* ba = (const float*)d_in[4];
    transpose_W_kernel<<<144, 256>>>((const float4*)W);
    cudaFuncSetAttribute(caps_kernel,
                         cudaFuncAttributeMaxDynamicSharedMemorySize,
                         SM_TOT * (int)sizeof(float));
    caps_kernel<<<NPOS, 512, SM_TOT * sizeof(float)>>>(x, a, bu, ba, (float*)d_out);
}

// round 9
// speedup vs baseline: 1.6633x; 1.1649x over previous
#include <cuda_runtime.h>

// ConvCapsMatrix: EM-routing matrix capsules, fully fused.
// B=4, 14x14 -> 12x12, KH=KW=3, IC=OC=32, M=4 (P=16), ITERS=3.
//
// R8 -> R9: resubmission — R8 hit an infra-side container failure and never
// ran. Contents: R6 kernel + hoisting of pass-invariant mu/sigma smem reads
// into registers (16 conflicted LDS.64 per chunk -> 16 per pass; ~18K L1
// cycles/CTA removed). Softmax stays shfl.bfly (redux.f32 rejected on sm_103).
// R5 -> R6 was W pre-transpose (coalesced LDG): 229.6 -> 162.3 us.
//
// Fusions: sig2 = E[V^2]-mu^2; R-update of iter i fused into accumulation
// of iter i+1; V recomputed per pass (never stored); pose math packed f32x2.
// Roles in a 512-thread CTA (one CTA per output position):
//  streaming: (nn = warp 0..15, o = lane 0..31); softmax over o = warp shfl
//  stats:     (o3 = tid>>4, p3 = tid&15)

#define NPOS  576           // 4 * 12 * 12
#define EPSF  1e-8f

// dynamic smem layout (float offsets)
#define SM_XP    0          // [4608]  x patch [n][p]
#define SM_A     4608       // [288]   a patch
#define SM_NMU   4896       // [576]   -mu, [o*18+p] (u64-pair readable)
#define SM_HSG   5472       // [576]   0.5/sig2, same layout
#define SM_SLOG  6048       // [32]
#define SM_LOGA  6080       // [32]
#define SM_RED1  6112       // [16*544] per-warp S1 partials [w*544+o*17+p], p=16 -> Rs
#define SM_RED2  14816      // [16*544] per-warp S2 partials
#define SM_TOT   23520      // floats -> 94080 bytes

typedef unsigned long long u64;

// transposed W: ulonglong2[(n*4+y)*32 + o] = W[n][o][y][0..3]  (576 KB scratch)
__device__ ulonglong2 g_Wt[288 * 4 * 32];

__device__ __forceinline__ u64 pk2(float lo, float hi) {
    u64 r; asm("mov.b64 %0, {%1, %2};" : "=l"(r) : "f"(lo), "f"(hi)); return r;
}
__device__ __forceinline__ void upk2(u64 v, float& lo, float& hi) {
    asm("mov.b64 {%0, %1}, %2;" : "=f"(lo), "=f"(hi) : "l"(v));
}
__device__ __forceinline__ u64 fma2(u64 a, u64 b, u64 c) {
    u64 d; asm("fma.rn.f32x2 %0, %1, %2, %3;" : "=l"(d) : "l"(a), "l"(b), "l"(c)); return d;
}
__device__ __forceinline__ u64 mul2(u64 a, u64 b) {
    u64 d; asm("mul.rn.f32x2 %0, %1, %2;" : "=l"(d) : "l"(a), "l"(b)); return d;
}
__device__ __forceinline__ u64 add2(u64 a, u64 b) {
    u64 d; asm("add.rn.f32x2 %0, %1, %2;" : "=l"(d) : "l"(a), "l"(b)); return d;
}

__global__ void __launch_bounds__(256)
transpose_W_kernel(const float4* __restrict__ W4)
{
    int idx = blockIdx.x * 256 + threadIdx.x;   // (n*4+y)*32 + o
    if (idx >= 288 * 4 * 32) return;
    int o  = idx & 31;
    int ny = idx >> 5;
    int y  = ny & 3;
    int n  = ny >> 2;
    float4 r = W4[(n * 32 + o) * 4 + y];
    ulonglong2 v;
    v.x = pk2(r.x, r.y);
    v.y = pk2(r.z, r.w);
    g_Wt[idx] = v;                               // coalesced 16B store
}

extern __shared__ float smem[];

__global__ void __launch_bounds__(512)
caps_kernel(const float* __restrict__ x, const float* __restrict__ a,
            const float* __restrict__ bu_g, const float* __restrict__ ba_g,
            float* __restrict__ out)
{
    const int tid = threadIdx.x;
    const int pos = blockIdx.x;
    const int b  = pos / 144;
    const int hw = pos - b * 144;
    const int h  = hw / 12;
    const int w  = hw - h * 12;

    // ---- load x / a patches into smem (coalesced) ----
    for (int idx = tid; idx < 4608; idx += 512) {
        int n = idx >> 4, q = idx & 15;
        int k = n / 96;
        int r = n - k * 96;
        int l = r >> 5;
        int c = r & 31;
        smem[SM_XP + idx] = x[(((b * 14 + h + k) * 14 + (w + l)) * 32 + c) * 16 + q];
    }
    if (tid < 288) {
        int n = tid;
        int k = n / 96;
        int r = n - k * 96;
        int l = r >> 5;
        int c = r & 31;
        smem[SM_A + n] = a[((b * 14 + h + k) * 14 + (w + l)) * 32 + c];
    }
    __syncthreads();

    const int lane_o  = tid & 31;   // streaming: output capsule
    const int warp_nn = tid >> 5;   // streaming: n within chunk
    const int o3 = tid >> 4;        // stats role
    const int p3 = tid & 15;

    const u64* nmu_p = reinterpret_cast<const u64*>(smem + SM_NMU) + lane_o * 9;
    const u64* hsg_p = reinterpret_cast<const u64*>(smem + SM_HSG) + lane_o * 9;
    float* row1 = smem + SM_RED1 + warp_nn * 544 + lane_o * 17;  // bank-bijective over o
    float* row2 = smem + SM_RED2 + warp_nn * 544 + lane_o * 17;
    // coalesced W: lane o reads g_Wt[(n*4+y)*32 + o]; chunk stride = 16*4*32
    const ulonglong2* Wbase = g_Wt + (warp_nn << 7) + lane_o;

    for (int pass = 0; pass < 3; ++pass) {
        u64 s1p[8], s2p[8];
        #pragma unroll
        for (int j = 0; j < 8; ++j) { s1p[j] = 0ull; s2p[j] = 0ull; }
        float rs_reg = 0.f;

        // pass-invariant per-o constants, hoisted to registers
        float pre = 0.f;
        u64 nmu_r[8], hsg_r[8];
        if (pass > 0) {
            pre = smem[SM_LOGA + lane_o] - 0.5f * smem[SM_SLOG + lane_o];
            #pragma unroll
            for (int j = 0; j < 8; ++j) { nmu_r[j] = nmu_p[j]; hsg_r[j] = hsg_p[j]; }
        }

        // prefetch chunk 0's W rows (4 coalesced LDG.128)
        const ulonglong2* wp = Wbase;
        ulonglong2 wy0 = wp[0], wy1 = wp[32], wy2 = wp[64], wy3 = wp[96];

        #pragma unroll 1
        for (int ch = 0; ch < 18; ++ch) {
            const int n = ch * 16 + warp_nn;
            const float4* xv = reinterpret_cast<const float4*>(smem + SM_XP) + (n << 2);

            // V[n, lane_o, :] packed: vp[2x+hh] = (v[4x+2hh], v[4x+2hh+1])
            u64 vp[8];
            #pragma unroll
            for (int xx = 0; xx < 4; ++xx) {
                float4 xr = xv[xx];
                u64 b0 = pk2(xr.x, xr.x);
                u64 b1 = pk2(xr.y, xr.y);
                u64 b2 = pk2(xr.z, xr.z);
                u64 b3 = pk2(xr.w, xr.w);
                u64 lo = mul2(b0, wy0.x);
                lo = fma2(b1, wy1.x, lo);
                lo = fma2(b2, wy2.x, lo);
                lo = fma2(b3, wy3.x, lo);
                u64 hi = mul2(b0, wy0.y);
                hi = fma2(b1, wy1.y, hi);
                hi = fma2(b2, wy2.y, hi);
                hi = fma2(b3, wy3.y, hi);
                vp[xx * 2]     = lo;
                vp[xx * 2 + 1] = hi;
            }

            // wy dead: issue next chunk's W loads now (covered by logp/accum)
            if (ch < 17) {
                wp += 2048;
                wy0 = wp[0]; wy1 = wp[32]; wy2 = wp[64]; wy3 = wp[96];
            }

            float Ra;
            if (pass == 0) {
                Ra = smem[SM_A + n] * 0.03125f;   // R uniform = 1/OC
            } else {
                // t = sum_p 0.5 * d^2 / sig2  (0.5 folded into hsg_r)
                u64 t2 = 0ull;
                #pragma unroll
                for (int j = 0; j < 8; ++j) {
                    u64 d = add2(vp[j], nmu_r[j]);   // mu stored negated
                    t2 = fma2(mul2(d, d), hsg_r[j], t2);
                }
                float tl, th; upk2(t2, tl, th);
                float s = pre - (tl + th);
                // softmax over o == softmax over warp lanes
                float m = s;
                #pragma unroll
                for (int off = 16; off; off >>= 1)
                    m = fmaxf(m, __shfl_xor_sync(0xffffffffu, m, off));
                float e = __expf(s - m);
                float sum = e;
                #pragma unroll
                for (int off = 16; off; off >>= 1)
                    sum += __shfl_xor_sync(0xffffffffu, sum, off);
                Ra = __fdividef(e, sum) * smem[SM_A + n];
            }

            rs_reg += Ra;
            u64 Ra2 = pk2(Ra, Ra);
            #pragma unroll
            for (int j = 0; j < 8; ++j) {
                u64 rv = mul2(Ra2, vp[j]);
                s1p[j] = add2(s1p[j], rv);
                s2p[j] = fma2(rv, vp[j], s2p[j]);
            }
        }

        // ---- cross-warp reduction: STS partials to this warp's private row ----
        row1[16] = rs_reg;                   // Rs in the p=16 pad slot
        #pragma unroll
        for (int j = 0; j < 8; ++j) {
            float lo, hi;
            upk2(s1p[j], lo, hi);
            row1[2 * j] = lo; row1[2 * j + 1] = hi;
            upk2(s2p[j], lo, hi);
            row2[2 * j] = lo; row2[2 * j + 1] = hi;
        }
        __syncthreads();

        // ---- gather + stats: thread (o3, p3) ----
        float sS1 = 0.f, sS2 = 0.f, sRs = 0.f;
        {
            const float* g1 = smem + SM_RED1 + o3 * 17 + p3;
            const float* g2 = smem + SM_RED2 + o3 * 17 + p3;
            const float* gr = smem + SM_RED1 + o3 * 17 + 16;
            #pragma unroll
            for (int ww = 0; ww < 16; ++ww) {
                sS1 += g1[ww * 544];
                sS2 += g2[ww * 544];
                sRs += gr[ww * 544];
            }
        }
        float Rsv   = sRs + EPSF;
        float invRs = 1.0f / Rsv;
        float mu    = sS1 * invRs;
        float sig2  = fmaxf(sS2 * invRs - mu * mu, 0.0f) + EPSF;
        float sl    = __logf(sig2);
        #pragma unroll
        for (int off = 8; off; off >>= 1)     // reduce log sig2 over 16 p-lanes
            sl += __shfl_xor_sync(0xffffffffu, sl, off);

        if (pass < 2) {
            smem[SM_NMU + o3 * 18 + p3] = -mu;
            smem[SM_HSG + o3 * 18 + p3] = __fdividef(0.5f, sig2);
            if (p3 == 0) {
                smem[SM_SLOG + o3] = sl;
                float cost = Rsv * fmaf(0.5f, sl, 16.0f * bu_g[o3]);
                float aout = 1.0f / (1.0f + __expf(cost - ba_g[o3]));
                smem[SM_LOGA + o3] = __logf(aout + EPSF);
            }
            __syncthreads();   // stats visible before next pass streams
        } else {
            // final iteration: emit pose (= mu) and activation
            out[pos * 512 + o3 * 16 + p3] = mu;
            if (p3 == 0) {
                float cost = Rsv * fmaf(0.5f, sl, 16.0f * bu_g[o3]);
                out[NPOS * 512 + pos * 32 + o3] =
                    1.0f / (1.0f + __expf(cost - ba_g[o3]));
            }
        }
    }
}

extern "C" void kernel_launch(void* const* d_in, const int* in_sizes, int n_in,
                              void* d_out, int out_size)
{
    (void)in_sizes; (void)n_in; (void)out_size;
    const float* x  = (const float*)d_in[0];
    const float* a  = (const float*)d_in[1];
    const float* W  = (const float*)d_in[2];
    const float* bu = (const float*)d_in[3];
    const float* ba = (const float*)d_in[4];
    transpose_W_kernel<<<144, 256>>>((const float4*)W);
    cudaFuncSetAttribute(caps_kernel,
                         cudaFuncAttributeMaxDynamicSharedMemorySize,
                         SM_TOT * (int)sizeof(float));
    caps_kernel<<<NPOS, 512, SM_TOT * sizeof(float)>>>(x, a, bu, ba, (float*)d_out);
}

// round 10
// speedup vs baseline: 1.9103x; 1.1485x over previous
#include <cuda_runtime.h>

// ConvCapsMatrix: EM-routing matrix capsules, fully fused.
// B=4, 14x14 -> 12x12, KH=KW=3, IC=OC=32, M=4 (P=16), ITERS=3.
//
// R9 -> R10: latency-bound profile (issue 41.6%, no pipe >46%).
//  (a) 256-thread CTAs, __launch_bounds__(256,2): two independent CTAs/SM
//      (same 128-reg/thread budget) so barriers + softmax chains of one CTA
//      overlap with the other's work; waves 3.89 -> 1.95.
//  (b) softmax max via integer redux.sync.max.u32 (monotone key mapping) —
//      one op instead of a 5-deep shfl chain; bitwise-identical max.
// History: R6 W pre-transpose 229.6->162.3; R9 mu/sigma reg-hoist ->139.3.
//
// Fusions: sig2 = E[V^2]-mu^2; R-update of iter i fused into accumulation
// of iter i+1; V recomputed per pass (never stored); pose math packed f32x2.
// Roles in a 256-thread CTA (one CTA per output position):
//  streaming: (nn = warp 0..7, o = lane 0..31); 36 chunks per warp
//  stats:     (o = tid>>4 and (tid>>4)+16, p = tid&15)

#define NPOS  576           // 4 * 12 * 12
#define EPSF  1e-8f

// dynamic smem layout (float offsets)
#define SM_XP    0          // [4608]  x patch [n][p]
#define SM_A     4608       // [288]   a patch
#define SM_NMU   4896       // [576]   -mu, [o*18+p] (u64-pair readable)
#define SM_HSG   5472       // [576]   0.5/sig2, same layout
#define SM_SLOG  6048       // [32]
#define SM_LOGA  6080       // [32]
#define SM_RED1  6112       // [8*544] per-warp S1 partials [w*544+o*17+p], p=16 -> Rs
#define SM_RED2  10464      // [8*544] per-warp S2 partials
#define SM_TOT   14816      // floats -> 59264 bytes

typedef unsigned long long u64;

// transposed W: ulonglong2[(n*4+y)*32 + o] = W[n][o][y][0..3]  (576 KB scratch)
__device__ ulonglong2 g_Wt[288 * 4 * 32];

__device__ __forceinline__ u64 pk2(float lo, float hi) {
    u64 r; asm("mov.b64 %0, {%1, %2};" : "=l"(r) : "f"(lo), "f"(hi)); return r;
}
__device__ __forceinline__ void upk2(u64 v, float& lo, float& hi) {
    asm("mov.b64 {%0, %1}, %2;" : "=f"(lo), "=f"(hi) : "l"(v));
}
__device__ __forceinline__ u64 fma2(u64 a, u64 b, u64 c) {
    u64 d; asm("fma.rn.f32x2 %0, %1, %2, %3;" : "=l"(d) : "l"(a), "l"(b), "l"(c)); return d;
}
__device__ __forceinline__ u64 mul2(u64 a, u64 b) {
    u64 d; asm("mul.rn.f32x2 %0, %1, %2;" : "=l"(d) : "l"(a), "l"(b)); return d;
}
__device__ __forceinline__ u64 add2(u64 a, u64 b) {
    u64 d; asm("add.rn.f32x2 %0, %1, %2;" : "=l"(d) : "l"(a), "l"(b)); return d;
}
// warp-max of a float via integer redux (monotone order-preserving key)
__device__ __forceinline__ float warp_max_f32(float s) {
    unsigned sb = __float_as_uint(s);
    unsigned key = sb ^ ((unsigned)(((int)sb) >> 31) | 0x80000000u);
    unsigned mk;
    asm("redux.sync.max.u32 %0, %1, 0xffffffff;" : "=r"(mk) : "r"(key));
    unsigned mb = mk ^ ((unsigned)(((int)(~mk)) >> 31) | 0x80000000u);
    return __uint_as_float(mb);
}

__global__ void __launch_bounds__(256)
transpose_W_kernel(const float4* __restrict__ W4)
{
    int idx = blockIdx.x * 256 + threadIdx.x;   // (n*4+y)*32 + o
    if (idx >= 288 * 4 * 32) return;
    int o  = idx & 31;
    int ny = idx >> 5;
    int y  = ny & 3;
    int n  = ny >> 2;
    float4 r = W4[(n * 32 + o) * 4 + y];
    ulonglong2 v;
    v.x = pk2(r.x, r.y);
    v.y = pk2(r.z, r.w);
    g_Wt[idx] = v;                               // coalesced 16B store
}

extern __shared__ float smem[];

__global__ void __launch_bounds__(256, 2)
caps_kernel(const float* __restrict__ x, const float* __restrict__ a,
            const float* __restrict__ bu_g, const float* __restrict__ ba_g,
            float* __restrict__ out)
{
    const int tid = threadIdx.x;
    const int pos = blockIdx.x;
    const int b  = pos / 144;
    const int hw = pos - b * 144;
    const int h  = hw / 12;
    const int w  = hw - h * 12;

    // ---- load x / a patches into smem (coalesced) ----
    for (int idx = tid; idx < 4608; idx += 256) {
        int n = idx >> 4, q = idx & 15;
        int k = n / 96;
        int r = n - k * 96;
        int l = r >> 5;
        int c = r & 31;
        smem[SM_XP + idx] = x[(((b * 14 + h + k) * 14 + (w + l)) * 32 + c) * 16 + q];
    }
    for (int n = tid; n < 288; n += 256) {
        int k = n / 96;
        int r = n - k * 96;
        int l = r >> 5;
        int c = r & 31;
        smem[SM_A + n] = a[((b * 14 + h + k) * 14 + (w + l)) * 32 + c];
    }
    __syncthreads();

    const int lane_o  = tid & 31;   // streaming: output capsule
    const int warp_nn = tid >> 5;   // streaming: n within chunk (0..7)
    const int oa = tid >> 4;        // stats role: first o (0..15)
    const int ob = oa + 16;         // stats role: second o
    const int p3 = tid & 15;

    const u64* nmu_p = reinterpret_cast<const u64*>(smem + SM_NMU) + lane_o * 9;
    const u64* hsg_p = reinterpret_cast<const u64*>(smem + SM_HSG) + lane_o * 9;
    float* row1 = smem + SM_RED1 + warp_nn * 544 + lane_o * 17;  // bank-bijective over o
    float* row2 = smem + SM_RED2 + warp_nn * 544 + lane_o * 17;
    // coalesced W: lane o reads g_Wt[(n*4+y)*32 + o]; chunk advance = 8*128 ull2
    const ulonglong2* Wbase = g_Wt + (warp_nn << 7) + lane_o;

    for (int pass = 0; pass < 3; ++pass) {
        u64 s1p[8], s2p[8];
        #pragma unroll
        for (int j = 0; j < 8; ++j) { s1p[j] = 0ull; s2p[j] = 0ull; }
        float rs_reg = 0.f;

        // pass-invariant per-o constants, hoisted to registers
        float pre = 0.f;
        u64 nmu_r[8], hsg_r[8];
        if (pass > 0) {
            pre = smem[SM_LOGA + lane_o] - 0.5f * smem[SM_SLOG + lane_o];
            #pragma unroll
            for (int j = 0; j < 8; ++j) { nmu_r[j] = nmu_p[j]; hsg_r[j] = hsg_p[j]; }
        }

        // prefetch chunk 0's W rows (4 coalesced LDG.128)
        const ulonglong2* wp = Wbase;
        ulonglong2 wy0 = wp[0], wy1 = wp[32], wy2 = wp[64], wy3 = wp[96];

        #pragma unroll 1
        for (int ch = 0; ch < 36; ++ch) {
            const int n = ch * 8 + warp_nn;
            const float4* xv = reinterpret_cast<const float4*>(smem + SM_XP) + (n << 2);

            // V[n, lane_o, :] packed: vp[2x+hh] = (v[4x+2hh], v[4x+2hh+1])
            u64 vp[8];
            #pragma unroll
            for (int xx = 0; xx < 4; ++xx) {
                float4 xr = xv[xx];
                u64 b0 = pk2(xr.x, xr.x);
                u64 b1 = pk2(xr.y, xr.y);
                u64 b2 = pk2(xr.z, xr.z);
                u64 b3 = pk2(xr.w, xr.w);
                u64 lo = mul2(b0, wy0.x);
                lo = fma2(b1, wy1.x, lo);
                lo = fma2(b2, wy2.x, lo);
                lo = fma2(b3, wy3.x, lo);
                u64 hi = mul2(b0, wy0.y);
                hi = fma2(b1, wy1.y, hi);
                hi = fma2(b2, wy2.y, hi);
                hi = fma2(b3, wy3.y, hi);
                vp[xx * 2]     = lo;
                vp[xx * 2 + 1] = hi;
            }

            // wy dead: issue next chunk's W loads now (covered by logp/accum)
            if (ch < 35) {
                wp += 1024;
                wy0 = wp[0]; wy1 = wp[32]; wy2 = wp[64]; wy3 = wp[96];
            }

            float Ra;
            if (pass == 0) {
                Ra = smem[SM_A + n] * 0.03125f;   // R uniform = 1/OC
            } else {
                // t = sum_p 0.5 * d^2 / sig2  (0.5 folded into hsg_r)
                u64 t2 = 0ull;
                #pragma unroll
                for (int j = 0; j < 8; ++j) {
                    u64 d = add2(vp[j], nmu_r[j]);   // mu stored negated
                    t2 = fma2(mul2(d, d), hsg_r[j], t2);
                }
                float tl, th; upk2(t2, tl, th);
                float s = pre - (tl + th);
                // softmax over o == softmax over warp lanes
                float m = warp_max_f32(s);           // single-op integer redux
                float e = __expf(s - m);
                float sum = e;
                #pragma unroll
                for (int off = 16; off; off >>= 1)
                    sum += __shfl_xor_sync(0xffffffffu, sum, off);
                Ra = __fdividef(e, sum) * smem[SM_A + n];
            }

            rs_reg += Ra;
            u64 Ra2 = pk2(Ra, Ra);
            #pragma unroll
            for (int j = 0; j < 8; ++j) {
                u64 rv = mul2(Ra2, vp[j]);
                s1p[j] = add2(s1p[j], rv);
                s2p[j] = fma2(rv, vp[j], s2p[j]);
            }
        }

        // ---- cross-warp reduction: STS partials to this warp's private row ----
        row1[16] = rs_reg;                   // Rs in the p=16 pad slot
        #pragma unroll
        for (int j = 0; j < 8; ++j) {
            float lo, hi;
            upk2(s1p[j], lo, hi);
            row1[2 * j] = lo; row1[2 * j + 1] = hi;
            upk2(s2p[j], lo, hi);
            row2[2 * j] = lo; row2[2 * j + 1] = hi;
        }
        __syncthreads();

        // ---- gather + stats: thread handles (oa, p3) and (ob, p3) ----
        #pragma unroll
        for (int half = 0; half < 2; ++half) {
            const int o3 = half ? ob : oa;
            float sS1 = 0.f, sS2 = 0.f, sRs = 0.f;
            {
                const float* g1 = smem + SM_RED1 + o3 * 17 + p3;
                const float* g2 = smem + SM_RED2 + o3 * 17 + p3;
                const float* gr = smem + SM_RED1 + o3 * 17 + 16;
                #pragma unroll
                for (int ww = 0; ww < 8; ++ww) {
                    sS1 += g1[ww * 544];
                    sS2 += g2[ww * 544];
                    sRs += gr[ww * 544];
                }
            }
            float Rsv   = sRs + EPSF;
            float invRs = 1.0f / Rsv;
            float mu    = sS1 * invRs;
            float sig2  = fmaxf(sS2 * invRs - mu * mu, 0.0f) + EPSF;
            float sl    = __logf(sig2);
            #pragma unroll
            for (int off = 8; off; off >>= 1)   // reduce log sig2 over 16 p-lanes
                sl += __shfl_xor_sync(0xffffffffu, sl, off);

            if (pass < 2) {
                smem[SM_NMU + o3 * 18 + p3] = -mu;
                smem[SM_HSG + o3 * 18 + p3] = __fdividef(0.5f, sig2);
                if (p3 == 0) {
                    smem[SM_SLOG + o3] = sl;
                    float cost = Rsv * fmaf(0.5f, sl, 16.0f * bu_g[o3]);
                    float aout = 1.0f / (1.0f + __expf(cost - ba_g[o3]));
                    smem[SM_LOGA + o3] = __logf(aout + EPSF);
                }
            } else {
                out[pos * 512 + o3 * 16 + p3] = mu;
                if (p3 == 0) {
                    float cost = Rsv * fmaf(0.5f, sl, 16.0f * bu_g[o3]);
                    out[NPOS * 512 + pos * 32 + o3] =
                        1.0f / (1.0f + __expf(cost - ba_g[o3]));
                }
            }
        }
        if (pass < 2) __syncthreads();   // stats visible before next pass streams
    }
}

extern "C" void kernel_launch(void* const* d_in, const int* in_sizes, int n_in,
                              void* d_out, int out_size)
{
    (void)in_sizes; (void)n_in; (void)out_size;
    const float* x  = (const float*)d_in[0];
    const float* a  = (const float*)d_in[1];
    const float* W  = (const float*)d_in[2];
    const float* bu = (const float*)d_in[3];
    const float* ba = (const float*)d_in[4];
    transpose_W_kernel<<<144, 256>>>((const float4*)W);
    cudaFuncSetAttribute(caps_kernel,
                         cudaFuncAttributeMaxDynamicSharedMemorySize,
                         SM_TOT * (int)sizeof(float));
    caps_kernel<<<NPOS, 256, SM_TOT * sizeof(float)>>>(x, a, bu, ba, (float*)d_out);
}